// round 12
// baseline (speedup 1.0000x reference)
#include <cuda_runtime.h>
#include <cuda_bf16.h>

#define FULLMASK 0xFFFFFFFFu
#define LOG2E 1.4426950408889634f

using u64 = unsigned long long;

__device__ __forceinline__ u64 fma2(u64 a, u64 b, u64 c) {
    u64 d; asm("fma.rn.f32x2 %0,%1,%2,%3;" : "=l"(d) : "l"(a), "l"(b), "l"(c)); return d;
}
__device__ __forceinline__ u64 add2(u64 a, u64 b) {
    u64 d; asm("add.rn.f32x2 %0,%1,%2;" : "=l"(d) : "l"(a), "l"(b)); return d;
}
__device__ __forceinline__ u64 bcast2(float v) {
    u64 d; asm("mov.b64 %0,{%1,%1};" : "=l"(d) : "f"(v)); return d;
}
__device__ __forceinline__ float2 unpk(u64 v) {
    float2 r; asm("mov.b64 {%0,%1},%2;" : "=f"(r.x), "=f"(r.y) : "l"(v)); return r;
}
__device__ __forceinline__ float ex2f(float x) {
    float r; asm("ex2.approx.f32 %0,%1;" : "=f"(r) : "f"(x)); return r;
}
__device__ __forceinline__ float rcpf(float x) {
    float r; asm("rcp.approx.f32 %0,%1;" : "=f"(r) : "f"(x)); return r;
}
__device__ __forceinline__ float rsqf(float x) {
    float r; asm("rsqrt.approx.f32 %0,%1;" : "=f"(r) : "f"(x)); return r;
}

union Row { ulonglong2 u; float4 f; };

// DUAL-TILE version of the R7 layout: each warp processes TWO independent
// 4-location tiles (A and B) concurrently, so tile B's FMA stream fills the
// latency bubbles of tile A's shfl/ex2 chains (ILP instead of occupancy).
//
// Per-tile layout (proven): 4 locations/tile, 8 lanes/location.
// t=lane&7, h=t>>2 (row-half), q=t&3 (d-quad). Lane holds 8 rows of its half
// in ROTATION ORDER: slot (k,j) -> row 2*((q+k)&3)+j, cols 4q..4q+3.
// Lane OWNS rows 8h+2q,8h+2q+1 (logits, exponentials). Quad comm via width-4
// shfl.idx with compile-time register slots; agree = ring reduce (partner at
// +k holds my rows' partials in slot (4-k)&3).
//
// b in log2-space; softmax 1/s cancels inside squash:
//   out = a*sq*rcp(s^2+sq)*rsq(sq+eps*s^2).   No max-subtract needed.
__global__ void __launch_bounds__(256, 2) routing_kernel(
    const float* __restrict__ pred,
    const float* __restrict__ b_in,
    const int*   __restrict__ nit,
    float*       __restrict__ out,
    int n_tiles, int ohw, int ohw_mask)
{
    const int lane = threadIdx.x & 31;
    const int t = lane & 7;
    const int h = t >> 2;
    const int q = t & 3;
    const int g = lane >> 3;
    const int s1 = (q + 1) & 3, s2 = (q + 2) & 3, s3 = (q + 3) & 3;

    const unsigned pair = blockIdx.x * (blockDim.x >> 5) + (threadIdx.x >> 5);
    const unsigned wA = pair * 2u;
    if (wA >= (unsigned)n_tiles) return;        // warp-uniform guard
    const unsigned wB = wA + 1u;
    const bool hasB = wB < (unsigned)n_tiles;
    const unsigned wBs = hasB ? wB : wA;        // safe address if odd count

    const int iters = *nit;
    const ulonglong2* p4 = reinterpret_cast<const ulonglong2*>(pred);
    const int base_off = 64 * g + 32 * h + q;

    // ---- both tiles: 16 coalesced LDG.128 over a contiguous 8KB span ----
    Row PA[8], PB[8];
    {
        const ulonglong2* pa = p4 + (size_t)wA * 256;
        const ulonglong2* pb = p4 + (size_t)wBs * 256;
#pragma unroll
        for (int k = 0; k < 4; ++k) {
            const int off = 8 * ((q + k) & 3);
            PA[2 * k].u     = pa[base_off + off];
            PA[2 * k + 1].u = pa[base_off + off + 4];
            PB[2 * k].u     = pb[base_off + off];
            PB[2 * k + 1].u = pb[base_off + off + 4];
        }
    }

    // ---- logits for owned rows of both tiles (log2-space) ----
    const unsigned locA = wA * 4u + g;
    const unsigned locB = wBs * 4u + g;
    float bA0, bA1, bB0, bB1;
    {
        const unsigned blocA = ohw_mask ? (locA & (unsigned)ohw_mask)
                                        : (locA % (unsigned)ohw);
        const unsigned blocB = ohw_mask ? (locB & (unsigned)ohw_mask)
                                        : (locB % (unsigned)ohw);
        const float2 a2 = *reinterpret_cast<const float2*>(
            b_in + (size_t)blocA * 16 + 8 * h + 2 * q);
        const float2 b2 = *reinterpret_cast<const float2*>(
            b_in + (size_t)blocB * 16 + 8 * h + 2 * q);
        bA0 = a2.x * LOG2E; bA1 = a2.y * LOG2E;
        bB0 = b2.x * LOG2E; bB1 = b2.y * LOG2E;
    }

    float oA0, oA1, oA2, oA3, oB0, oB1, oB2, oB3;

    // one routing pass over BOTH tiles, interleaved for ILP
    auto pass = [&]() {
        const float eA0 = ex2f(bA0), eA1 = ex2f(bA1);
        const float eB0 = ex2f(bB0), eB1 = ex2f(bB1);
        float eA[8], eB[8];
        eA[0] = eA0; eA[1] = eA1;
        eB[0] = eB0; eB[1] = eB1;
        eA[2] = __shfl_sync(FULLMASK, eA0, s1, 4);
        eB[2] = __shfl_sync(FULLMASK, eB0, s1, 4);
        eA[3] = __shfl_sync(FULLMASK, eA1, s1, 4);
        eB[3] = __shfl_sync(FULLMASK, eB1, s1, 4);
        eA[4] = __shfl_sync(FULLMASK, eA0, s2, 4);
        eB[4] = __shfl_sync(FULLMASK, eB0, s2, 4);
        eA[5] = __shfl_sync(FULLMASK, eA1, s2, 4);
        eB[5] = __shfl_sync(FULLMASK, eB1, s2, 4);
        eA[6] = __shfl_sync(FULLMASK, eA0, s3, 4);
        eB[6] = __shfl_sync(FULLMASK, eB0, s3, 4);
        eA[7] = __shfl_sync(FULLMASK, eA1, s3, 4);
        eB[7] = __shfl_sync(FULLMASK, eB1, s3, 4);

        float sA = ((eA[0]+eA[1])+(eA[2]+eA[3])) + ((eA[4]+eA[5])+(eA[6]+eA[7]));
        float sB = ((eB[0]+eB[1])+(eB[2]+eB[3])) + ((eB[4]+eB[5])+(eB[6]+eB[7]));
        sA += __shfl_xor_sync(FULLMASK, sA, 4);
        sB += __shfl_xor_sync(FULLMASK, sB, 4);

        u64 xA01 = 0ull, xA23 = 0ull, xB01 = 0ull, xB23 = 0ull;
#pragma unroll
        for (int r = 0; r < 8; ++r) {
            const u64 ea = bcast2(eA[r]);
            const u64 eb = bcast2(eB[r]);
            xA01 = fma2(ea, PA[r].u.x, xA01);
            xB01 = fma2(eb, PB[r].u.x, xB01);
            xA23 = fma2(ea, PA[r].u.y, xA23);
            xB23 = fma2(eb, PB[r].u.y, xB23);
        }
        xA01 = add2(xA01, __shfl_xor_sync(FULLMASK, xA01, 4));
        xB01 = add2(xB01, __shfl_xor_sync(FULLMASK, xB01, 4));
        xA23 = add2(xA23, __shfl_xor_sync(FULLMASK, xA23, 4));
        xB23 = add2(xB23, __shfl_xor_sync(FULLMASK, xB23, 4));

        float2 loA = unpk(xA01), hiA = unpk(xA23);
        float2 loB = unpk(xB01), hiB = unpk(xB23);
        const float aA0 = loA.x, aA1 = loA.y, aA2 = hiA.x, aA3 = hiA.y;
        const float aB0 = loB.x, aB1 = loB.y, aB2 = hiB.x, aB3 = hiB.y;

        float sqA = fmaf(aA3, aA3, fmaf(aA2, aA2, fmaf(aA1, aA1, aA0 * aA0)));
        float sqB = fmaf(aB3, aB3, fmaf(aB2, aB2, fmaf(aB1, aB1, aB0 * aB0)));
        sqA += __shfl_xor_sync(FULLMASK, sqA, 1);
        sqB += __shfl_xor_sync(FULLMASK, sqB, 1);
        sqA += __shfl_xor_sync(FULLMASK, sqA, 2);
        sqB += __shfl_xor_sync(FULLMASK, sqB, 2);

        const float s2A = sA * sA;
        const float s2B = sB * sB;
        const float fA = sqA * rcpf(s2A + sqA) * rsqf(fmaf(1e-7f, s2A, sqA));
        const float fB = sqB * rcpf(s2B + sqB) * rsqf(fmaf(1e-7f, s2B, sqB));
        oA0 = aA0 * fA; oA1 = aA1 * fA; oA2 = aA2 * fA; oA3 = aA3 * fA;
        oB0 = aB0 * fB; oB1 = aB1 * fB; oB2 = aB2 * fB; oB3 = aB3 * fB;
    };

    pass();
    for (int it = 0; it < iters; ++it) {
        float pA[8], pB[8];
#pragma unroll
        for (int m = 0; m < 8; ++m) {
            pA[m] = fmaf(PA[m].f.w, oA3, fmaf(PA[m].f.z, oA2,
                    fmaf(PA[m].f.y, oA1, PA[m].f.x * oA0)));
            pB[m] = fmaf(PB[m].f.w, oB3, fmaf(PB[m].f.z, oB2,
                    fmaf(PB[m].f.y, oB1, PB[m].f.x * oB0)));
        }
        const float rA10 = __shfl_sync(FULLMASK, pA[6], s1, 4);
        const float rB10 = __shfl_sync(FULLMASK, pB[6], s1, 4);
        const float rA11 = __shfl_sync(FULLMASK, pA[7], s1, 4);
        const float rB11 = __shfl_sync(FULLMASK, pB[7], s1, 4);
        const float rA20 = __shfl_sync(FULLMASK, pA[4], s2, 4);
        const float rB20 = __shfl_sync(FULLMASK, pB[4], s2, 4);
        const float rA21 = __shfl_sync(FULLMASK, pA[5], s2, 4);
        const float rB21 = __shfl_sync(FULLMASK, pB[5], s2, 4);
        const float rA30 = __shfl_sync(FULLMASK, pA[2], s3, 4);
        const float rB30 = __shfl_sync(FULLMASK, pB[2], s3, 4);
        const float rA31 = __shfl_sync(FULLMASK, pA[3], s3, 4);
        const float rB31 = __shfl_sync(FULLMASK, pB[3], s3, 4);

        bA0 = fmaf((pA[0] + rA10) + (rA20 + rA30), LOG2E, bA0);
        bB0 = fmaf((pB[0] + rB10) + (rB20 + rB30), LOG2E, bB0);
        bA1 = fmaf((pA[1] + rA11) + (rA21 + rA31), LOG2E, bA1);
        bB1 = fmaf((pB[1] + rB11) + (rB21 + rB31), LOG2E, bB1);
        pass();
    }

    if (h == 0) {
        reinterpret_cast<float4*>(out)[(size_t)locA * 4 + q] =
            make_float4(oA0, oA1, oA2, oA3);
        if (hasB)
            reinterpret_cast<float4*>(out)[(size_t)locB * 4 + q] =
                make_float4(oB0, oB1, oB2, oB3);
    }
}

extern "C" void kernel_launch(void* const* d_in, const int* in_sizes, int n_in,
                              void* d_out, int out_size) {
    const float* pred = (const float*)d_in[0];
    const float* b    = (const float*)d_in[1];
    const int*   nit  = (const int*)d_in[2];
    float* out = (float*)d_out;

    const int n_loc = in_sizes[0] / 256;   // B*O*H*W
    const int ohw   = in_sizes[1] / 16;    // O*H*W
    const int ohw_mask = ((ohw & (ohw - 1)) == 0) ? (ohw - 1) : 0;

    const int n_tiles = (n_loc + 3) / 4;   // 4-location tiles
    const int n_pairs = (n_tiles + 1) / 2; // 2 tiles per warp
    const int blocks  = (n_pairs + 7) / 8; // 8 warps per block
    routing_kernel<<<blocks, 256>>>(pred, b, nit, out, n_tiles, ohw, ohw_mask);
}